// round 15
// baseline (speedup 1.0000x reference)
#include <cuda_runtime.h>
#include <cuda_bf16.h>

// Quantum circuit: N_QUBITS=10 (N=1024), N_LAYERS=5, out = U @ state per (b,c).
// R15: register-resident sim, f32x2 packs TWO STATES (lo/hi halves run the
// identical circuit), 4 warps per state-pair (CTA=128), SITES=8.
// Physical index p (after GF(2) basis transform T = diag(I5, B)):
//   bits 0-4 = lane, 5-7 = site, 8-9 = warp.   (pack = state index, no bit)
// State/thread: X[s] = f32x2(re stateA, re stateB), Y[s] = imag pack.
// vs R14: coeff packs store pre-negated .y entries (4 ull/variant, not 6),
// __launch_bounds__(128,6) for 24 warps/SM, and cross-warp exchanges are
// double-buffered (1 barrier per cross gate).
//
// ENDIANNESS: qubit q (axis q+1) is bit (NQ-1-q) of the flattened index.

#define NQ      10
#define NST     1024
#define NLAYERS 5
#define NGATES  (NLAYERS * NQ)
#define NSTATES 2048          // 128 * 16
#define BLOCK   128
#define SITES   8

typedef unsigned long long ull;

__host__ __device__ constexpr int highest_bit(unsigned v) {
    int h = 0; while (v >>= 1) h++; return h;
}
__host__ __device__ constexpr int parity10(unsigned x) {
    int p = 0;
    for (int k = 0; k < NQ; k++) p ^= (int)((x >> k) & 1u);
    return p;
}
__host__ __device__ constexpr int popc64(unsigned long long v) {
    int c = 0; while (v) { v &= v - 1; c++; } return c;
}

struct M5 { unsigned r[5]; };

__host__ __device__ constexpr M5 gf2inv5(M5 A) {
    unsigned a[5] = {}, b[5] = {};
    for (int i = 0; i < 5; i++) { a[i] = A.r[i]; b[i] = 1u << i; }
    for (int c = 0; c < 5; c++) {
        int p = c;
        for (int i = c; i < 5; i++) if ((a[i] >> c) & 1u) { p = i; break; }
        unsigned ta = a[c]; a[c] = a[p]; a[p] = ta;
        unsigned tb = b[c]; b[c] = b[p]; b[p] = tb;
        for (int i = 0; i < 5; i++)
            if (i != c && ((a[i] >> c) & 1u)) { a[i] ^= a[c]; b[i] ^= b[c]; }
    }
    M5 R{};
    for (int i = 0; i < 5; i++) R.r[i] = b[i];
    return R;
}

__host__ __device__ constexpr bool indep(const unsigned* vs, int n, unsigned cand) {
    unsigned a[6] = {};
    for (int i = 0; i < n; i++) a[i] = vs[i];
    a[n] = cand;
    int rank = 0;
    for (int bit = 4; bit >= 0; bit--) {
        int piv = -1;
        for (int i = rank; i <= n; i++) if ((a[i] >> bit) & 1u) { piv = i; break; }
        if (piv < 0) continue;
        unsigned t = a[rank]; a[rank] = a[piv]; a[piv] = t;
        for (int i = 0; i <= n; i++)
            if (i != rank && ((a[i] >> bit) & 1u)) a[i] ^= a[rank];
        rank++;
    }
    return rank == n + 1;
}

struct Plan {
    unsigned m[NGATES];      // physical pair mask
    unsigned s[NGATES];      // physical parity mask
    unsigned lrow[32];       // load map per (warp<<3 | site)
    unsigned jreg[32];       // store map per (warp<<3 | site)
    unsigned rlow[NQ];       // rows_final[b] & 31 (lane contribution)
};

__host__ __device__ constexpr void run_circuit(unsigned (&rows)[NQ], unsigned (&cols)[NQ],
                                               unsigned* m_out, unsigned* s_out) {
    int g = 0;
    for (int l = NLAYERS - 1; l >= 0; l--) {
        for (int q = NQ - 1; q >= 0; q--) {
            int c = NQ - 1 - q;                 // control bit
            int t = NQ - 1 - ((q + 1) % NQ);    // target bit
            rows[t] ^= rows[c];
            cols[c] ^= cols[t];
        }
        for (int q = NQ - 1; q >= 0; q--) {
            int b = NQ - 1 - q;
            if (m_out) m_out[g] = cols[b];
            if (s_out) s_out[g] = rows[b];
            g++;
        }
    }
}

__host__ __device__ constexpr Plan make_plan() {
    // Pass 1: identity basis, raw masks, to choose B (bitset-accelerated).
    unsigned m0[NGATES] = {};
    {
        unsigned rows[NQ] = {}, cols[NQ] = {};
        for (int r = 0; r < NQ; r++) { rows[r] = 1u << r; cols[r] = 1u << r; }
        run_circuit(rows, cols, m0, nullptr);
    }
    unsigned char par5[32] = {};
    for (unsigned v = 0; v < 32; v++) {
        unsigned x = v; int p = 0;
        while (x) { p ^= (int)(x & 1u); x >>= 1; }
        par5[v] = (unsigned char)p;
    }
    unsigned mu[NGATES] = {};
    for (int g = 0; g < NGATES; g++) mu[g] = (m0[g] >> 5) & 31u;
    unsigned long long gmask[32] = {};
    for (unsigned r = 1; r < 32; r++) {
        unsigned long long msk = 0;
        for (int g = 0; g < NGATES; g++)
            if (par5[mu[g] & r]) msk |= 1ull << g;
        gmask[r] = msk;
    }
    // Warp rows (Binv rows 3,4): minimize # cross-warp gates.
    unsigned bwa = 1, bwb = 2; int bestw = NGATES + 1;
    for (unsigned wa = 1; wa < 32; wa++)
        for (unsigned wb = wa + 1; wb < 32; wb++) {
            int c = popc64(gmask[wa] | gmask[wb]);
            if (c < bestw) { bestw = c; bwa = wa; bwb = wb; }
        }
    unsigned cur[5] = {bwa, bwb, 0, 0, 0};
    int have = 2;
    for (unsigned cand = 1; cand < 32 && have < 5; cand++)
        if (indep(cur, have, cand)) cur[have++] = cand;
    M5 Binv{};
    Binv.r[3] = bwa; Binv.r[4] = bwb;
    Binv.r[0] = cur[2]; Binv.r[1] = cur[3]; Binv.r[2] = cur[4];
    M5 B = gf2inv5(Binv);

    Plan P{};
    // Pass 2: full plan with phi initialized to T = diag(I5, B).
    unsigned rows[NQ] = {}, cols[NQ] = {};
    for (int b = 0; b < 5; b++) { rows[b] = 1u << b; cols[b] = 1u << b; }
    for (int i = 0; i < 5; i++) {
        rows[5 + i] = B.r[i] << 5;
        unsigned colv = 0;                       // column i of Binv
        for (int j = 0; j < 5; j++) colv |= ((Binv.r[j] >> i) & 1u) << j;
        cols[5 + i] = colv << 5;
    }
    run_circuit(rows, cols, P.m, P.s);

    for (unsigned preg = 0; preg < 32; preg++) {
        unsigned R = 0;
        for (int i = 0; i < 5; i++) R |= (unsigned)parity10(preg & B.r[i]) << i;
        P.lrow[preg] = R;
    }
    for (unsigned preg = 0; preg < 32; preg++) {
        unsigned j = 0;
        for (int b = 0; b < NQ; b++)
            j ^= (unsigned)parity10((preg << 5) & rows[b]) << b;
        P.jreg[preg] = j;
    }
    for (int b = 0; b < NQ; b++) P.rlow[b] = rows[b] & 31u;
    return P;
}

static constexpr Plan PLAN = make_plan();

// # of cross-warp gates before gate G (for double-buffer parity).
__host__ __device__ constexpr int cross_before(int G) {
    int c = 0;
    for (int g = 0; g < G; g++)
        if ((PLAN.m[g] >> 8) & 3u) c++;
    return c;
}

// ---------------- packed f32x2 helpers ----------------
__device__ __forceinline__ ull fma2(ull a, ull b, ull c) {
    ull d;
    asm("fma.rn.f32x2 %0, %1, %2, %3;" : "=l"(d) : "l"(a), "l"(b), "l"(c));
    return d;
}
__device__ __forceinline__ ull mul2(ull a, ull b) {
    ull d;
    asm("mul.rn.f32x2 %0, %1, %2;" : "=l"(d) : "l"(a), "l"(b));
    return d;
}
__device__ __forceinline__ ull packf(float lo, float hi) {
    ull d;
    asm("mov.b64 %0, {%1, %2};" : "=l"(d) : "f"(lo), "f"(hi));
    return d;
}
__device__ __forceinline__ void unpackf(float& lo, float& hi, ull v) {
    asm("mov.b64 {%0, %1}, %2;" : "=f"(lo), "=f"(hi) : "l"(v));
}
__device__ __forceinline__ ull neg2(ull v) { return v ^ 0x8000000080000000ull; }

// Per-gate coeff packs (both f32x2 halves identical): variant v = role:
//   [0] = cs.x   [1] = -cs.y   [2] = cp.x   [3] = -cp.y     (y pre-negated)
// where cs(0)=c00, cs(1)=c11, cp(0)=c01, cp(1)=c10.
__device__ ull g_packs[NGATES][2][4];

// Coefficients for applying G^T to the vector:
//   n0 =  cos(th/2)*a0          + e^{i ph} sin(th/2)*a1
//   n1 = -e^{i lm} sin(th/2)*a0 + e^{i(ph+lm)} cos(th/2)*a1
__global__ void prep_gates_kernel(const float* __restrict__ w, int w_elems) {
    int e = threadIdx.x;
    if (e >= NGATES) return;
    int l = (NLAYERS - 1) - e / NQ;     // matches plan emission order
    int q = (NQ - 1) - e % NQ;
    int base = (l * NQ + q) * 3;
    float th = 0.f, ph = 0.f, lm = 0.f;
    if (base + 2 < w_elems) { th = w[base]; ph = w[base + 1]; lm = w[base + 2]; }
    float c, s;
    sincosf(0.5f * th, &s, &c);
    float cp_, sp_;   sincosf(ph, &sp_, &cp_);
    float cl, sl;     sincosf(lm, &sl, &cl);
    float cpl, spl;   sincosf(ph + lm, &spl, &cpl);
    float2 c00 = make_float2(c, 0.0f);
    float2 c01 = make_float2(cp_ * s, sp_ * s);
    float2 c10 = make_float2(-cl * s, -sl * s);
    float2 c11 = make_float2(cpl * c, spl * c);

    for (int v = 0; v < 2; v++) {
        float2 cs = v ? c11 : c00;
        float2 cp = v ? c10 : c01;
        g_packs[e][v][0] = packf(cs.x,  cs.x);
        g_packs[e][v][1] = packf(-cs.y, -cs.y);
        g_packs[e][v][2] = packf(cp.x,  cp.x);
        g_packs[e][v][3] = packf(-cp.y, -cp.y);
    }
}

// Masks as template parameters. BUF = double-buffer index for cross gates.
template <int G, unsigned M, unsigned S, int BUF>
__device__ __forceinline__ void apply_gate(ull (&X)[SITES], ull (&Y)[SITES],
                                           int lane, int wid, int tid,
                                           ull (*exX)[SITES][BLOCK],
                                           ull (*exY)[SITES][BLOCK]) {
    constexpr unsigned ML = M & 31u;          // lane part
    constexpr unsigned MR = (M >> 5) & 7u;    // site part
    constexpr unsigned MW = (M >> 8) & 3u;    // warp part
    constexpr unsigned SL = S & 31u;
    constexpr unsigned SR = (S >> 5) & 7u;
    constexpr unsigned SW = (S >> 8) & 3u;

    // beta = runtime (lane,warp) parity; ct = compile-time site parity.
    const int beta = (__popc(lane & (int)SL) ^ __popc(wid & (int)SW)) & 1;
    const ull* PA = &g_packs[G][beta][0];         // variant for ct = 0
    const ull A0 = __ldg(PA + 0), A1 = __ldg(PA + 1), A2 = __ldg(PA + 2), A3 = __ldg(PA + 3);

    ull B0 = A0, B1 = A1, B2 = A2, B3 = A3;
    if constexpr (SR != 0) {                      // ct=1 variant actually used
        const ull* PB = &g_packs[G][beta ^ 1][0];
        B0 = __ldg(PB + 0); B1 = __ldg(PB + 1); B2 = __ldg(PB + 2); B3 = __ldg(PB + 3);
    }

    // Butterfly (complex, packed over 2 states), with CSYn = -cs.y, CPYn = -cp.y:
    //   nX = CSX*X + CSYn*Y      + CPX*wX + CPYn*wY
    //   nY = CSX*Y + CSYn*(-X)   + CPX*wY + CPYn*(-wX)
    auto upd = [&](int s, ull wX, ull wY) {
        const bool ct = parity10((unsigned)s & SR) != 0;   // s literal -> folds
        const ull CSX  = ct ? B0 : A0;
        const ull CSYn = ct ? B1 : A1;
        const ull CPX  = ct ? B2 : A2;
        const ull CPYn = ct ? B3 : A3;
        ull nX = fma2(CSX, X[s], fma2(CSYn, Y[s],       fma2(CPX, wX, mul2(CPYn, wY))));
        ull nY = fma2(CSX, Y[s], fma2(CSYn, neg2(X[s]), fma2(CPX, wY, mul2(CPYn, neg2(wX)))));
        X[s] = nX; Y[s] = nY;
    };

    if constexpr (MW != 0) {
        // Cross-warp: exchange via double-buffered smem (1 barrier per gate).
        #pragma unroll
        for (int s = 0; s < SITES; s++) { exX[BUF][s][tid] = X[s]; exY[BUF][s][tid] = Y[s]; }
        __syncthreads();
        const int ptid = tid ^ (int)(ML | (MW << 5));
        #pragma unroll
        for (int s = 0; s < SITES; s++) {
            ull wX = exX[BUF][s ^ (int)MR][ptid];
            ull wY = exY[BUF][s ^ (int)MR][ptid];
            upd(s, wX, wY);
        }
    } else if constexpr (MR != 0) {
        constexpr int HB = highest_bit(MR);
        #pragma unroll
        for (int s = 0; s < SITES; s++) {
            if ((s >> HB) & 1) continue;
            const int s2 = s ^ (int)MR;
            ull aX = X[s], aY = Y[s], bX = X[s2], bY = Y[s2];
            if constexpr (ML != 0) {
                aX = __shfl_xor_sync(0xffffffffu, aX, (int)ML);
                aY = __shfl_xor_sync(0xffffffffu, aY, (int)ML);
                bX = __shfl_xor_sync(0xffffffffu, bX, (int)ML);
                bY = __shfl_xor_sync(0xffffffffu, bY, (int)ML);
            }
            upd(s,  bX, bY);   // partner of s  lives at site s2
            upd(s2, aX, aY);   // partner of s2 lives at site s (old value)
        }
    } else {
        // Lane-only gate (M != 0 always, so ML != 0 here).
        #pragma unroll
        for (int s = 0; s < SITES; s++) {
            ull wX = __shfl_xor_sync(0xffffffffu, X[s], (int)ML);
            ull wY = __shfl_xor_sync(0xffffffffu, Y[s], (int)ML);
            upd(s, wX, wY);
        }
    }
}

template <int G>
struct GateSeq {
    static __device__ __forceinline__ void run(ull (&X)[SITES], ull (&Y)[SITES],
                                               int lane, int wid, int tid,
                                               ull (*exX)[SITES][BLOCK],
                                               ull (*exY)[SITES][BLOCK]) {
        apply_gate<G, PLAN.m[G], PLAN.s[G], (cross_before(G) & 1)>(
            X, Y, lane, wid, tid, exX, exY);
        GateSeq<G + 1>::run(X, Y, lane, wid, tid, exX, exY);
    }
};
template <>
struct GateSeq<NGATES> {
    static __device__ __forceinline__ void run(ull (&)[SITES], ull (&)[SITES],
                                               int, int, int,
                                               ull (*)[SITES][BLOCK],
                                               ull (*)[SITES][BLOCK]) {}
};

struct PParam {
    unsigned short lrow[32];
    unsigned short jreg[32];
    unsigned char  rlow[NQ];
};

template <int OUT_MODE>   // 0 = real-only float, 1 = interleaved float2
__global__ __launch_bounds__(BLOCK, 6)
void sim_kernel(const float* __restrict__ x, int x_elems,
                void* __restrict__ outv, int out_size, PParam pp) {
    __shared__ ull exX[2][SITES][BLOCK];
    __shared__ ull exY[2][SITES][BLOCK];

    const int tid  = threadIdx.x;
    const int lane = tid & 31;
    const int wid  = tid >> 5;
    const long long base0 = (long long)(2 * blockIdx.x) * NST;      // state A
    const long long base1 = base0 + NST;                            // state B

    ull X[SITES], Y[SITES];
    #pragma unroll
    for (int s = 0; s < SITES; s++) {
        int row = pp.lrow[(wid << 3) | s];
        int off = (row << 5) + lane;                                // coalesced
        long long g0 = base0 + off, g1 = base1 + off;
        float x0 = (g0 < x_elems) ? x[g0] : 0.0f;
        float x1 = (g1 < x_elems) ? x[g1] : 0.0f;
        X[s] = packf(x0, x1);
        Y[s] = 0ull;
    }

    GateSeq<0>::run(X, Y, lane, wid, tid, exX, exY);

    unsigned jl = 0;
    #pragma unroll
    for (int b = 0; b < NQ; b++)
        jl ^= (unsigned)((__popc(lane & (int)pp.rlow[b]) & 1) << b);

    #pragma unroll
    for (int s = 0; s < SITES; s++) {
        unsigned j = (unsigned)pp.jreg[(wid << 3) | s] ^ jl;
        float x0, x1, y0, y1;
        unpackf(x0, x1, X[s]);
        unpackf(y0, y1, Y[s]);
        long long o0 = base0 + j, o1 = base1 + j;
        if (OUT_MODE == 0) {
            if (o0 < out_size) ((float*)outv)[o0] = x0;
            if (o1 < out_size) ((float*)outv)[o1] = x1;
        } else {
            if (2 * o0 + 1 < out_size) ((float2*)outv)[o0] = make_float2(x0, y0);
            if (2 * o1 + 1 < out_size) ((float2*)outv)[o1] = make_float2(x1, y1);
        }
    }
}

extern "C" void kernel_launch(void* const* d_in, const int* in_sizes, int n_in,
                              void* d_out, int out_size) {
    const float* x_freq  = nullptr;  int x_elems = 0;
    const float* weights = nullptr;  int w_elems = 0;
    for (int i = 0; i < n_in; i++) {
        if (in_sizes[i] >= NSTATES * NST && !x_freq) {
            x_freq = (const float*)d_in[i]; x_elems = in_sizes[i];
        } else if (in_sizes[i] == NLAYERS * NQ * 3 && !weights) {
            weights = (const float*)d_in[i]; w_elems = in_sizes[i];
        }
    }
    if (!x_freq || !weights) {
        int big = 0;
        for (int i = 1; i < n_in; i++) if (in_sizes[i] > in_sizes[big]) big = i;
        x_freq = (const float*)d_in[big]; x_elems = in_sizes[big];
        int sm = (big == 0 && n_in > 1) ? 1 : 0;
        weights = (const float*)d_in[sm]; w_elems = in_sizes[sm];
    }

    prep_gates_kernel<<<1, 64>>>(weights, w_elems);

    PParam pp;
    for (int i = 0; i < 32; i++) pp.lrow[i] = (unsigned short)PLAN.lrow[i];
    for (int i = 0; i < 32; i++) pp.jreg[i] = (unsigned short)PLAN.jreg[i];
    for (int b = 0; b < NQ; b++) pp.rlow[b] = (unsigned char)PLAN.rlow[b];

    // out_size == 2M -> real float32 output; >= 4M -> interleaved complex64.
    if (out_size <= NSTATES * NST)
        sim_kernel<0><<<NSTATES / 2, BLOCK>>>(x_freq, x_elems, d_out, out_size, pp);
    else
        sim_kernel<1><<<NSTATES / 2, BLOCK>>>(x_freq, x_elems, d_out, out_size, pp);
}

// round 16
// speedup vs baseline: 1.1624x; 1.1624x over previous
#include <cuda_runtime.h>
#include <cuda_bf16.h>

// Quantum circuit: N_QUBITS=10 (N=1024), N_LAYERS=5, out = U @ state per (b,c).
// R16: register-resident sim, f32x2 packs TWO STATES; 8 warps per state-pair
// (CTA=256), SITES=4 -> state is only 16 regs/thread, so occupancy comes from
// low demand (~55 regs), not from a deficit cap (R13/R15 spill lesson).
// Physical index p (after GF(2) basis transform T = diag(I5, B)):
//   bits 0-4 = lane, 5-6 = site, 7-9 = warp.   (pack = state index, no bit)
// State/thread: X[s] = f32x2(re stateA, re stateB), Y[s] = imag pack.
// Coeff packs pre-negate the .y entries (4 ull/variant, R15-verified algebra).
// Basis search: 3-dim warp subspace minimizing cross-warp gates.
//
// ENDIANNESS: qubit q (axis q+1) is bit (NQ-1-q) of the flattened index.

#define NQ      10
#define NST     1024
#define NLAYERS 5
#define NGATES  (NLAYERS * NQ)
#define NSTATES 2048          // 128 * 16
#define BLOCK   256
#define SITES   4

typedef unsigned long long ull;

__host__ __device__ constexpr int highest_bit(unsigned v) {
    int h = 0; while (v >>= 1) h++; return h;
}
__host__ __device__ constexpr int parity10(unsigned x) {
    int p = 0;
    for (int k = 0; k < NQ; k++) p ^= (int)((x >> k) & 1u);
    return p;
}
__host__ __device__ constexpr int popc64(unsigned long long v) {
    int c = 0; while (v) { v &= v - 1; c++; } return c;
}

struct M5 { unsigned r[5]; };

__host__ __device__ constexpr M5 gf2inv5(M5 A) {
    unsigned a[5] = {}, b[5] = {};
    for (int i = 0; i < 5; i++) { a[i] = A.r[i]; b[i] = 1u << i; }
    for (int c = 0; c < 5; c++) {
        int p = c;
        for (int i = c; i < 5; i++) if ((a[i] >> c) & 1u) { p = i; break; }
        unsigned ta = a[c]; a[c] = a[p]; a[p] = ta;
        unsigned tb = b[c]; b[c] = b[p]; b[p] = tb;
        for (int i = 0; i < 5; i++)
            if (i != c && ((a[i] >> c) & 1u)) { a[i] ^= a[c]; b[i] ^= b[c]; }
    }
    M5 R{};
    for (int i = 0; i < 5; i++) R.r[i] = b[i];
    return R;
}

__host__ __device__ constexpr bool indep(const unsigned* vs, int n, unsigned cand) {
    unsigned a[6] = {};
    for (int i = 0; i < n; i++) a[i] = vs[i];
    a[n] = cand;
    int rank = 0;
    for (int bit = 4; bit >= 0; bit--) {
        int piv = -1;
        for (int i = rank; i <= n; i++) if ((a[i] >> bit) & 1u) { piv = i; break; }
        if (piv < 0) continue;
        unsigned t = a[rank]; a[rank] = a[piv]; a[piv] = t;
        for (int i = 0; i <= n; i++)
            if (i != rank && ((a[i] >> bit) & 1u)) a[i] ^= a[rank];
        rank++;
    }
    return rank == n + 1;
}

struct Plan {
    unsigned m[NGATES];      // physical pair mask
    unsigned s[NGATES];      // physical parity mask
    unsigned lrow[32];       // load map per (warp<<2 | site)
    unsigned jreg[32];       // store map per (warp<<2 | site)
    unsigned rlow[NQ];       // rows_final[b] & 31 (lane contribution)
};

__host__ __device__ constexpr void run_circuit(unsigned (&rows)[NQ], unsigned (&cols)[NQ],
                                               unsigned* m_out, unsigned* s_out) {
    int g = 0;
    for (int l = NLAYERS - 1; l >= 0; l--) {
        for (int q = NQ - 1; q >= 0; q--) {
            int c = NQ - 1 - q;                 // control bit
            int t = NQ - 1 - ((q + 1) % NQ);    // target bit
            rows[t] ^= rows[c];
            cols[c] ^= cols[t];
        }
        for (int q = NQ - 1; q >= 0; q--) {
            int b = NQ - 1 - q;
            if (m_out) m_out[g] = cols[b];
            if (s_out) s_out[g] = rows[b];
            g++;
        }
    }
}

__host__ __device__ constexpr Plan make_plan() {
    // Pass 1: identity basis, raw masks, to choose B (bitset-accelerated).
    unsigned m0[NGATES] = {};
    {
        unsigned rows[NQ] = {}, cols[NQ] = {};
        for (int r = 0; r < NQ; r++) { rows[r] = 1u << r; cols[r] = 1u << r; }
        run_circuit(rows, cols, m0, nullptr);
    }
    unsigned char par5[32] = {};
    for (unsigned v = 0; v < 32; v++) {
        unsigned x = v; int p = 0;
        while (x) { p ^= (int)(x & 1u); x >>= 1; }
        par5[v] = (unsigned char)p;
    }
    unsigned mu[NGATES] = {};
    for (int g = 0; g < NGATES; g++) mu[g] = (m0[g] >> 5) & 31u;
    unsigned long long gmask[32] = {};
    for (unsigned r = 1; r < 32; r++) {
        unsigned long long msk = 0;
        for (int g = 0; g < NGATES; g++)
            if (par5[mu[g] & r]) msk |= 1ull << g;
        gmask[r] = msk;
    }
    // Warp rows (Binv rows 2,3,4): minimize # cross-warp gates.
    // Greedy: exhaustive best pair, then best independent third.
    unsigned bwa = 1, bwb = 2; int bestw = NGATES + 1;
    for (unsigned wa = 1; wa < 32; wa++)
        for (unsigned wb = wa + 1; wb < 32; wb++) {
            int c = popc64(gmask[wa] | gmask[wb]);
            if (c < bestw) { bestw = c; bwa = wa; bwb = wb; }
        }
    unsigned long long wm2 = gmask[bwa] | gmask[bwb];
    unsigned bwc = 0; int best3 = NGATES + 1;
    for (unsigned wc = 1; wc < 32; wc++) {
        if (wc == bwa || wc == bwb || wc == (bwa ^ bwb)) continue;
        int c = popc64(wm2 | gmask[wc]);
        if (c < best3) { best3 = c; bwc = wc; }
    }
    unsigned cur[5] = {bwa, bwb, bwc, 0, 0};
    int have = 3;
    for (unsigned cand = 1; cand < 32 && have < 5; cand++)
        if (indep(cur, have, cand)) cur[have++] = cand;
    M5 Binv{};
    Binv.r[2] = bwa; Binv.r[3] = bwb; Binv.r[4] = bwc;
    Binv.r[0] = cur[3]; Binv.r[1] = cur[4];
    M5 B = gf2inv5(Binv);

    Plan P{};
    // Pass 2: full plan with phi initialized to T = diag(I5, B).
    unsigned rows[NQ] = {}, cols[NQ] = {};
    for (int b = 0; b < 5; b++) { rows[b] = 1u << b; cols[b] = 1u << b; }
    for (int i = 0; i < 5; i++) {
        rows[5 + i] = B.r[i] << 5;
        unsigned colv = 0;                       // column i of Binv
        for (int j = 0; j < 5; j++) colv |= ((Binv.r[j] >> i) & 1u) << j;
        cols[5 + i] = colv << 5;
    }
    run_circuit(rows, cols, P.m, P.s);

    for (unsigned preg = 0; preg < 32; preg++) {
        unsigned R = 0;
        for (int i = 0; i < 5; i++) R |= (unsigned)parity10(preg & B.r[i]) << i;
        P.lrow[preg] = R;
    }
    for (unsigned preg = 0; preg < 32; preg++) {
        unsigned j = 0;
        for (int b = 0; b < NQ; b++)
            j ^= (unsigned)parity10((preg << 5) & rows[b]) << b;
        P.jreg[preg] = j;
    }
    for (int b = 0; b < NQ; b++) P.rlow[b] = rows[b] & 31u;
    return P;
}

static constexpr Plan PLAN = make_plan();

// ---------------- packed f32x2 helpers ----------------
__device__ __forceinline__ ull fma2(ull a, ull b, ull c) {
    ull d;
    asm("fma.rn.f32x2 %0, %1, %2, %3;" : "=l"(d) : "l"(a), "l"(b), "l"(c));
    return d;
}
__device__ __forceinline__ ull mul2(ull a, ull b) {
    ull d;
    asm("mul.rn.f32x2 %0, %1, %2;" : "=l"(d) : "l"(a), "l"(b));
    return d;
}
__device__ __forceinline__ ull packf(float lo, float hi) {
    ull d;
    asm("mov.b64 %0, {%1, %2};" : "=l"(d) : "f"(lo), "f"(hi));
    return d;
}
__device__ __forceinline__ void unpackf(float& lo, float& hi, ull v) {
    asm("mov.b64 {%0, %1}, %2;" : "=f"(lo), "=f"(hi) : "l"(v));
}
__device__ __forceinline__ ull neg2(ull v) { return v ^ 0x8000000080000000ull; }

// Per-gate coeff packs (both f32x2 halves identical): variant v = role:
//   [0] = cs.x   [1] = -cs.y   [2] = cp.x   [3] = -cp.y     (y pre-negated)
// where cs(0)=c00, cs(1)=c11, cp(0)=c01, cp(1)=c10.
__device__ ull g_packs[NGATES][2][4];

// Coefficients for applying G^T to the vector:
//   n0 =  cos(th/2)*a0          + e^{i ph} sin(th/2)*a1
//   n1 = -e^{i lm} sin(th/2)*a0 + e^{i(ph+lm)} cos(th/2)*a1
__global__ void prep_gates_kernel(const float* __restrict__ w, int w_elems) {
    int e = threadIdx.x;
    if (e >= NGATES) return;
    int l = (NLAYERS - 1) - e / NQ;     // matches plan emission order
    int q = (NQ - 1) - e % NQ;
    int base = (l * NQ + q) * 3;
    float th = 0.f, ph = 0.f, lm = 0.f;
    if (base + 2 < w_elems) { th = w[base]; ph = w[base + 1]; lm = w[base + 2]; }
    float c, s;
    sincosf(0.5f * th, &s, &c);
    float cp_, sp_;   sincosf(ph, &sp_, &cp_);
    float cl, sl;     sincosf(lm, &sl, &cl);
    float cpl, spl;   sincosf(ph + lm, &spl, &cpl);
    float2 c00 = make_float2(c, 0.0f);
    float2 c01 = make_float2(cp_ * s, sp_ * s);
    float2 c10 = make_float2(-cl * s, -sl * s);
    float2 c11 = make_float2(cpl * c, spl * c);

    for (int v = 0; v < 2; v++) {
        float2 cs = v ? c11 : c00;
        float2 cp = v ? c10 : c01;
        g_packs[e][v][0] = packf(cs.x,  cs.x);
        g_packs[e][v][1] = packf(-cs.y, -cs.y);
        g_packs[e][v][2] = packf(cp.x,  cp.x);
        g_packs[e][v][3] = packf(-cp.y, -cp.y);
    }
}

// Masks as template parameters.
template <int G, unsigned M, unsigned S>
__device__ __forceinline__ void apply_gate(ull (&X)[SITES], ull (&Y)[SITES],
                                           int lane, int wid, int tid,
                                           ull (*exX)[BLOCK], ull (*exY)[BLOCK]) {
    constexpr unsigned ML = M & 31u;          // lane part
    constexpr unsigned MR = (M >> 5) & 3u;    // site part (2 bits)
    constexpr unsigned MW = (M >> 7) & 7u;    // warp part (3 bits)
    constexpr unsigned SL = S & 31u;
    constexpr unsigned SR = (S >> 5) & 3u;
    constexpr unsigned SW = (S >> 7) & 7u;

    // beta = runtime (lane,warp) parity; ct = compile-time site parity.
    const int beta = (__popc(lane & (int)SL) ^ __popc(wid & (int)SW)) & 1;
    const ull* PA = &g_packs[G][beta][0];         // variant for ct = 0
    const ull A0 = __ldg(PA + 0), A1 = __ldg(PA + 1), A2 = __ldg(PA + 2), A3 = __ldg(PA + 3);

    ull B0 = A0, B1 = A1, B2 = A2, B3 = A3;
    if constexpr (SR != 0) {                      // ct=1 variant actually used
        const ull* PB = &g_packs[G][beta ^ 1][0];
        B0 = __ldg(PB + 0); B1 = __ldg(PB + 1); B2 = __ldg(PB + 2); B3 = __ldg(PB + 3);
    }

    // Butterfly (complex, packed over 2 states), with CSYn = -cs.y, CPYn = -cp.y:
    //   nX = CSX*X + CSYn*Y      + CPX*wX + CPYn*wY
    //   nY = CSX*Y + CSYn*(-X)   + CPX*wY + CPYn*(-wX)
    auto upd = [&](int s, ull wX, ull wY) {
        const bool ct = parity10((unsigned)s & SR) != 0;   // s literal -> folds
        const ull CSX  = ct ? B0 : A0;
        const ull CSYn = ct ? B1 : A1;
        const ull CPX  = ct ? B2 : A2;
        const ull CPYn = ct ? B3 : A3;
        ull nX = fma2(CSX, X[s], fma2(CSYn, Y[s],       fma2(CPX, wX, mul2(CPYn, wY))));
        ull nY = fma2(CSX, Y[s], fma2(CSYn, neg2(X[s]), fma2(CPX, wY, mul2(CPYn, neg2(wX)))));
        X[s] = nX; Y[s] = nY;
    };

    if constexpr (MW != 0) {
        // Cross-warp: exchange via smem (single buffer, 2 barriers).
        __syncthreads();
        #pragma unroll
        for (int s = 0; s < SITES; s++) { exX[s][tid] = X[s]; exY[s][tid] = Y[s]; }
        __syncthreads();
        const int ptid = tid ^ (int)(ML | (MW << 5));
        #pragma unroll
        for (int s = 0; s < SITES; s++) {
            ull wX = exX[s ^ (int)MR][ptid];
            ull wY = exY[s ^ (int)MR][ptid];
            upd(s, wX, wY);
        }
    } else if constexpr (MR != 0) {
        constexpr int HB = highest_bit(MR);
        #pragma unroll
        for (int s = 0; s < SITES; s++) {
            if ((s >> HB) & 1) continue;
            const int s2 = s ^ (int)MR;
            ull aX = X[s], aY = Y[s], bX = X[s2], bY = Y[s2];
            if constexpr (ML != 0) {
                aX = __shfl_xor_sync(0xffffffffu, aX, (int)ML);
                aY = __shfl_xor_sync(0xffffffffu, aY, (int)ML);
                bX = __shfl_xor_sync(0xffffffffu, bX, (int)ML);
                bY = __shfl_xor_sync(0xffffffffu, bY, (int)ML);
            }
            upd(s,  bX, bY);   // partner of s  lives at site s2
            upd(s2, aX, aY);   // partner of s2 lives at site s (old value)
        }
    } else {
        // Lane-only gate (M != 0 always, so ML != 0 here).
        #pragma unroll
        for (int s = 0; s < SITES; s++) {
            ull wX = __shfl_xor_sync(0xffffffffu, X[s], (int)ML);
            ull wY = __shfl_xor_sync(0xffffffffu, Y[s], (int)ML);
            upd(s, wX, wY);
        }
    }
}

template <int G>
struct GateSeq {
    static __device__ __forceinline__ void run(ull (&X)[SITES], ull (&Y)[SITES],
                                               int lane, int wid, int tid,
                                               ull (*exX)[BLOCK], ull (*exY)[BLOCK]) {
        apply_gate<G, PLAN.m[G], PLAN.s[G]>(X, Y, lane, wid, tid, exX, exY);
        GateSeq<G + 1>::run(X, Y, lane, wid, tid, exX, exY);
    }
};
template <>
struct GateSeq<NGATES> {
    static __device__ __forceinline__ void run(ull (&)[SITES], ull (&)[SITES],
                                               int, int, int,
                                               ull (*)[BLOCK], ull (*)[BLOCK]) {}
};

struct PParam {
    unsigned short lrow[32];
    unsigned short jreg[32];
    unsigned char  rlow[NQ];
};

template <int OUT_MODE>   // 0 = real-only float, 1 = interleaved float2
__global__ __launch_bounds__(BLOCK, 4)
void sim_kernel(const float* __restrict__ x, int x_elems,
                void* __restrict__ outv, int out_size, PParam pp) {
    __shared__ ull exX[SITES][BLOCK];
    __shared__ ull exY[SITES][BLOCK];

    const int tid  = threadIdx.x;
    const int lane = tid & 31;
    const int wid  = tid >> 5;
    const long long base0 = (long long)(2 * blockIdx.x) * NST;      // state A
    const long long base1 = base0 + NST;                            // state B

    ull X[SITES], Y[SITES];
    #pragma unroll
    for (int s = 0; s < SITES; s++) {
        int row = pp.lrow[(wid << 2) | s];
        int off = (row << 5) + lane;                                // coalesced
        long long g0 = base0 + off, g1 = base1 + off;
        float x0 = (g0 < x_elems) ? x[g0] : 0.0f;
        float x1 = (g1 < x_elems) ? x[g1] : 0.0f;
        X[s] = packf(x0, x1);
        Y[s] = 0ull;
    }

    GateSeq<0>::run(X, Y, lane, wid, tid, exX, exY);

    unsigned jl = 0;
    #pragma unroll
    for (int b = 0; b < NQ; b++)
        jl ^= (unsigned)((__popc(lane & (int)pp.rlow[b]) & 1) << b);

    #pragma unroll
    for (int s = 0; s < SITES; s++) {
        unsigned j = (unsigned)pp.jreg[(wid << 2) | s] ^ jl;
        float x0, x1, y0, y1;
        unpackf(x0, x1, X[s]);
        unpackf(y0, y1, Y[s]);
        long long o0 = base0 + j, o1 = base1 + j;
        if (OUT_MODE == 0) {
            if (o0 < out_size) ((float*)outv)[o0] = x0;
            if (o1 < out_size) ((float*)outv)[o1] = x1;
        } else {
            if (2 * o0 + 1 < out_size) ((float2*)outv)[o0] = make_float2(x0, y0);
            if (2 * o1 + 1 < out_size) ((float2*)outv)[o1] = make_float2(x1, y1);
        }
    }
}

extern "C" void kernel_launch(void* const* d_in, const int* in_sizes, int n_in,
                              void* d_out, int out_size) {
    const float* x_freq  = nullptr;  int x_elems = 0;
    const float* weights = nullptr;  int w_elems = 0;
    for (int i = 0; i < n_in; i++) {
        if (in_sizes[i] >= NSTATES * NST && !x_freq) {
            x_freq = (const float*)d_in[i]; x_elems = in_sizes[i];
        } else if (in_sizes[i] == NLAYERS * NQ * 3 && !weights) {
            weights = (const float*)d_in[i]; w_elems = in_sizes[i];
        }
    }
    if (!x_freq || !weights) {
        int big = 0;
        for (int i = 1; i < n_in; i++) if (in_sizes[i] > in_sizes[big]) big = i;
        x_freq = (const float*)d_in[big]; x_elems = in_sizes[big];
        int sm = (big == 0 && n_in > 1) ? 1 : 0;
        weights = (const float*)d_in[sm]; w_elems = in_sizes[sm];
    }

    prep_gates_kernel<<<1, 64>>>(weights, w_elems);

    PParam pp;
    for (int i = 0; i < 32; i++) pp.lrow[i] = (unsigned short)PLAN.lrow[i];
    for (int i = 0; i < 32; i++) pp.jreg[i] = (unsigned short)PLAN.jreg[i];
    for (int b = 0; b < NQ; b++) pp.rlow[b] = (unsigned char)PLAN.rlow[b];

    // out_size == 2M -> real float32 output; >= 4M -> interleaved complex64.
    if (out_size <= NSTATES * NST)
        sim_kernel<0><<<NSTATES / 2, BLOCK>>>(x_freq, x_elems, d_out, out_size, pp);
    else
        sim_kernel<1><<<NSTATES / 2, BLOCK>>>(x_freq, x_elems, d_out, out_size, pp);
}

// round 17
// speedup vs baseline: 1.4450x; 1.2431x over previous
#include <cuda_runtime.h>
#include <cuda_bf16.h>

// Quantum circuit: N_QUBITS=10 (N=1024), N_LAYERS=5, out = U @ state per (b,c).
// R17 = R7 (61.9us champion: 2 warps/state, CTA=64, 16 regs/lane) with the
// butterfly converted to COMPLEX-PACKED f32x2: v = (re, im) in one 64-bit reg.
//   n = A*v + B*sw(v) + C*w + D*sw(w),  sw = halves swapped,
//   A=(cs.x,cs.x) B=(-cs.y,cs.y) C=(cp.x,cp.x) D=(-cp.y,cp.y)
// -> 4 fma-pipe ops per butterfly output instead of 8 scalar FFMA.
// Index space, plan, masks, exchange paths are byte-identical to R7.
//
// ENDIANNESS: qubit q (axis q+1) is bit (NQ-1-q) of the flattened index.

#define NQ      10
#define NST     1024
#define NLAYERS 5
#define NGATES  (NLAYERS * NQ)
#define NSTATES 2048          // 128 * 16
#define BLOCK   64
#define REGS    16

typedef unsigned long long ull;

__host__ __device__ constexpr int highest_bit(unsigned v) {
    int h = 0; while (v >>= 1) h++; return h;
}
__host__ __device__ constexpr int parity10(unsigned x) {
    int p = 0;
    for (int k = 0; k < NQ; k++) p ^= (int)((x >> k) & 1u);
    return p;
}

struct M5 { unsigned r[5]; };   // 5x5 GF(2) matrix as row masks

__host__ __device__ constexpr M5 gf2inv5(M5 A) {
    unsigned a[5] = {}, b[5] = {};
    for (int i = 0; i < 5; i++) { a[i] = A.r[i]; b[i] = 1u << i; }
    for (int c = 0; c < 5; c++) {
        int p = c;
        for (int i = c; i < 5; i++) if ((a[i] >> c) & 1u) { p = i; break; }
        unsigned ta = a[c]; a[c] = a[p]; a[p] = ta;
        unsigned tb = b[c]; b[c] = b[p]; b[p] = tb;
        for (int i = 0; i < 5; i++)
            if (i != c && ((a[i] >> c) & 1u)) { a[i] ^= a[c]; b[i] ^= b[c]; }
    }
    M5 R{};
    for (int i = 0; i < 5; i++) R.r[i] = b[i];
    return R;
}

__host__ __device__ constexpr bool indep(const unsigned* vs, int n, unsigned cand) {
    unsigned a[6] = {};
    for (int i = 0; i < n; i++) a[i] = vs[i];
    a[n] = cand;
    int rank = 0;
    for (int bit = 4; bit >= 0; bit--) {
        int piv = -1;
        for (int i = rank; i <= n; i++) if ((a[i] >> bit) & 1u) { piv = i; break; }
        if (piv < 0) continue;
        unsigned t = a[rank]; a[rank] = a[piv]; a[piv] = t;
        for (int i = 0; i <= n; i++)
            if (i != rank && ((a[i] >> bit) & 1u)) a[i] ^= a[rank];
        rank++;
    }
    return rank == n + 1;
}

struct Plan {
    unsigned m[NGATES];      // physical pair mask
    unsigned s[NGATES];      // physical parity mask
    unsigned lrow[32];       // load: v-row per preg = (warp<<4)|reg
    unsigned jreg[32];       // store: index contribution of (warp,reg)
    unsigned rlow[NQ];       // store: rows_final[b] & 31 (lane contribution)
};

__host__ __device__ constexpr void run_circuit(unsigned (&rows)[NQ], unsigned (&cols)[NQ],
                                               unsigned* m_out, unsigned* s_out) {
    int g = 0;
    for (int l = NLAYERS - 1; l >= 0; l--) {
        for (int q = NQ - 1; q >= 0; q--) {
            int c = NQ - 1 - q;                 // control bit
            int t = NQ - 1 - ((q + 1) % NQ);    // target bit
            rows[t] ^= rows[c];
            cols[c] ^= cols[t];
        }
        for (int q = NQ - 1; q >= 0; q--) {
            int b = NQ - 1 - q;
            if (m_out) m_out[g] = cols[b];
            if (s_out) s_out[g] = rows[b];
            g++;
        }
    }
}

__host__ __device__ constexpr Plan make_plan() {
    // Pass 1: identity basis -> raw masks, to pick the basis B.
    unsigned m0[NGATES] = {};
    {
        unsigned rows[NQ] = {}, cols[NQ] = {};
        for (int r = 0; r < NQ; r++) { rows[r] = 1u << r; cols[r] = 1u << r; }
        run_circuit(rows, cols, m0, nullptr);
    }
    // Choose row4 of Binv (warp bit) minimizing # cross-warp gates.
    unsigned rbest = 1; int best = NGATES + 1;
    for (unsigned r = 1; r < 32; r++) {
        int cnt = 0;
        for (int g = 0; g < NGATES; g++)
            cnt += parity10(((m0[g] >> 5) & 31u) & r);
        if (cnt < best) { best = cnt; rbest = r; }
    }
    unsigned cur[5] = {rbest, 0, 0, 0, 0};
    int have = 1;
    for (unsigned cand = 1; cand < 32 && have < 5; cand++)
        if (indep(cur, have, cand)) cur[have++] = cand;
    M5 Binv{};
    Binv.r[4] = rbest;
    for (int i = 0; i < 4; i++) Binv.r[i] = cur[1 + i];
    M5 B = gf2inv5(Binv);

    Plan P{};
    // Pass 2: full plan with phi initialized to T = diag(I5, B).
    unsigned rows[NQ] = {}, cols[NQ] = {};
    for (int b = 0; b < 5; b++) { rows[b] = 1u << b; cols[b] = 1u << b; }
    for (int i = 0; i < 5; i++) {
        rows[5 + i] = B.r[i] << 5;
        unsigned colv = 0;                       // column i of Binv
        for (int j = 0; j < 5; j++) colv |= ((Binv.r[j] >> i) & 1u) << j;
        cols[5 + i] = colv << 5;
    }
    run_circuit(rows, cols, P.m, P.s);

    for (unsigned preg = 0; preg < 32; preg++) {
        unsigned R = 0;
        for (int i = 0; i < 5; i++) R |= (unsigned)parity10(preg & B.r[i]) << i;
        P.lrow[preg] = R;
    }
    for (unsigned preg = 0; preg < 32; preg++) {
        unsigned j = 0;
        for (int b = 0; b < NQ; b++)
            j ^= (unsigned)parity10((preg << 5) & rows[b]) << b;
        P.jreg[preg] = j;
    }
    for (int b = 0; b < NQ; b++) P.rlow[b] = rows[b] & 31u;
    return P;
}

static constexpr Plan PLAN = make_plan();

// ---------------- packed f32x2 helpers ----------------
__device__ __forceinline__ ull fma2(ull a, ull b, ull c) {
    ull d;
    asm("fma.rn.f32x2 %0, %1, %2, %3;" : "=l"(d) : "l"(a), "l"(b), "l"(c));
    return d;
}
__device__ __forceinline__ ull mul2(ull a, ull b) {
    ull d;
    asm("mul.rn.f32x2 %0, %1, %2;" : "=l"(d) : "l"(a), "l"(b));
    return d;
}
__device__ __forceinline__ ull packf(float lo, float hi) {
    ull d;
    asm("mov.b64 %0, {%1, %2};" : "=l"(d) : "f"(lo), "f"(hi));
    return d;
}
__device__ __forceinline__ void unpackf(float& lo, float& hi, ull v) {
    asm("mov.b64 {%0, %1}, %2;" : "=f"(lo), "=f"(hi) : "l"(v));
}
__device__ __forceinline__ ull swap64(ull v) {
    float lo, hi;
    unpackf(lo, hi, v);
    return packf(hi, lo);
}

// Per-gate coeff packs, variant v = role of the output slot:
//   [0] A = ( cs.x,  cs.x)   [1] B = (-cs.y, cs.y)
//   [2] C = ( cp.x,  cp.x)   [3] D = (-cp.y, cp.y)
// where cs(0)=c00, cs(1)=c11, cp(0)=c01, cp(1)=c10.
// Then cs*v = fma2(A, v) + fma2(B, swap(v)) with v = (re, im).
__device__ ull g_packs[NGATES][2][4];

// Coefficients for applying G^T to the vector:
//   n0 =  cos(th/2)*a0          + e^{i ph} sin(th/2)*a1
//   n1 = -e^{i lm} sin(th/2)*a0 + e^{i(ph+lm)} cos(th/2)*a1
__global__ void prep_gates_kernel(const float* __restrict__ w, int w_elems) {
    int e = threadIdx.x;
    if (e >= NGATES) return;
    int l = (NLAYERS - 1) - e / NQ;     // matches plan emission order
    int q = (NQ - 1) - e % NQ;
    int base = (l * NQ + q) * 3;
    float th = 0.f, ph = 0.f, lm = 0.f;
    if (base + 2 < w_elems) { th = w[base]; ph = w[base + 1]; lm = w[base + 2]; }
    float c, s;
    sincosf(0.5f * th, &s, &c);
    float cp_, sp_;   sincosf(ph, &sp_, &cp_);
    float cl, sl;     sincosf(lm, &sl, &cl);
    float cpl, spl;   sincosf(ph + lm, &spl, &cpl);
    float2 c00 = make_float2(c, 0.0f);
    float2 c01 = make_float2(cp_ * s, sp_ * s);
    float2 c10 = make_float2(-cl * s, -sl * s);
    float2 c11 = make_float2(cpl * c, spl * c);

    for (int v = 0; v < 2; v++) {
        float2 cs = v ? c11 : c00;
        float2 cp = v ? c10 : c01;
        g_packs[e][v][0] = packf(cs.x,  cs.x);
        g_packs[e][v][1] = packf(-cs.y, cs.y);
        g_packs[e][v][2] = packf(cp.x,  cp.x);
        g_packs[e][v][3] = packf(-cp.y, cp.y);
    }
}

// Masks as template parameters (no PLAN access in device code).
template <int G, unsigned M, unsigned S>
__device__ __forceinline__ void apply_gate(ull (&v)[REGS], int lane, int wid,
                                           ull (*sm)[BLOCK]) {
    constexpr unsigned ML = M & 31u;          // lane part
    constexpr unsigned MR = (M >> 5) & 15u;   // register part
    constexpr unsigned MW = M >> 9;           // warp part
    constexpr unsigned SL = S & 31u;
    constexpr unsigned SR = (S >> 5) & 15u;
    constexpr unsigned SW = S >> 9;

    // role(p) = parity(p & S) = runtime (lane,warp) parity ^ CT reg parity.
    const int beta = (__popc(lane & (int)SL) ^ (wid & (int)SW)) & 1;
    const ull* P0 = &g_packs[G][beta][0];         // reg-parity 0 variant
    const ull A0 = __ldg(P0 + 0), B0 = __ldg(P0 + 1), C0 = __ldg(P0 + 2), D0 = __ldg(P0 + 3);

    ull A1 = A0, B1 = B0, C1 = C0, D1 = D0;
    if constexpr (SR != 0) {
        const ull* P1 = &g_packs[G][beta ^ 1][0];
        A1 = __ldg(P1 + 0); B1 = __ldg(P1 + 1); C1 = __ldg(P1 + 2); D1 = __ldg(P1 + 3);
    }

    // n = A*v + B*sw(v) + C*w + D*sw(w)   (complex mult in packed form)
    auto upd = [&](int s, ull w) {
        const bool rp = (__popc((unsigned)s & SR) & 1) != 0;   // s literal -> folds
        const ull A = rp ? A1 : A0;
        const ull B = rp ? B1 : B0;
        const ull C = rp ? C1 : C0;
        const ull D = rp ? D1 : D0;
        v[s] = fma2(A, v[s], fma2(B, swap64(v[s]), fma2(C, w, mul2(D, swap64(w)))));
    };

    if constexpr (MW != 0) {
        // Cross-warp gate: exchange via shared memory.
        const int tid = (wid << 5) | lane;
        __syncthreads();
        #pragma unroll
        for (int r = 0; r < REGS; r++) sm[r][tid] = v[r];
        __syncthreads();
        const int ptid = tid ^ 32 ^ (int)ML;      // partner thread (other warp)
        #pragma unroll
        for (int r = 0; r < REGS; r++)
            upd(r, sm[r ^ (int)MR][ptid]);
    } else if constexpr (MR == 0) {
        // partner in same register, other lane
        #pragma unroll
        for (int r = 0; r < REGS; r++) {
            ull w = __shfl_xor_sync(0xffffffffu, v[r], (int)ML);
            upd(r, w);
        }
    } else {
        constexpr int HB = highest_bit(MR);
        #pragma unroll
        for (int r = 0; r < REGS; r++) {
            if ((r >> HB) & 1) continue;          // each pair handled once
            const int r2 = r ^ (int)MR;
            ull a = v[r], b = v[r2];
            if constexpr (ML != 0) {
                a = __shfl_xor_sync(0xffffffffu, a, (int)ML);
                b = __shfl_xor_sync(0xffffffffu, b, (int)ML);
            }
            upd(r,  b);     // partner of r  lives at slot r2 (old value)
            upd(r2, a);     // partner of r2 lives at slot r  (old value)
        }
    }
}

template <int G>
struct GateSeq {
    static __device__ __forceinline__ void run(ull (&v)[REGS], int lane, int wid,
                                               ull (*sm)[BLOCK]) {
        apply_gate<G, PLAN.m[G], PLAN.s[G]>(v, lane, wid, sm);
        GateSeq<G + 1>::run(v, lane, wid, sm);
    }
};
template <>
struct GateSeq<NGATES> {
    static __device__ __forceinline__ void run(ull (&)[REGS], int, int,
                                               ull (*)[BLOCK]) {}
};

struct PParam {
    unsigned short lrow[32];
    unsigned short jreg[32];
    unsigned char  rlow[NQ];
};

template <int OUT_MODE>   // 0 = real-only float, 1 = interleaved float2
__global__ __launch_bounds__(BLOCK)
void sim_kernel(const float* __restrict__ x, int x_elems,
                void* __restrict__ outv, int out_size, PParam pp) {
    __shared__ ull sm[REGS][BLOCK];

    const int tid  = threadIdx.x;
    const int lane = tid & 31;
    const int wid  = tid >> 5;
    const long long base = (long long)blockIdx.x * NST;

    ull v[REGS];
    #pragma unroll
    for (int r = 0; r < REGS; r++) {
        int row = pp.lrow[(wid << 4) | r];
        long long gi = base + (row << 5) + lane;          // coalesced per warp
        float re = (gi < x_elems) ? x[gi] : 0.0f;
        v[r] = packf(re, 0.0f);                           // (re, im)
    }

    GateSeq<0>::run(v, lane, wid, sm);

    // out[phi(p)] = slot p ;  phi(p) = jreg(warp,reg) ^ jlane(lane)
    unsigned jl = 0;
    #pragma unroll
    for (int b = 0; b < NQ; b++)
        jl ^= (unsigned)((__popc(lane & (int)pp.rlow[b]) & 1) << b);

    #pragma unroll
    for (int r = 0; r < REGS; r++) {
        unsigned j = (unsigned)pp.jreg[(wid << 4) | r] ^ jl;
        long long oi = base + j;
        float re, im;
        unpackf(re, im, v[r]);
        if (OUT_MODE == 0) {
            if (oi < out_size) ((float*)outv)[oi] = re;
        } else {
            if (2 * oi + 1 < out_size) ((float2*)outv)[oi] = make_float2(re, im);
        }
    }
}

extern "C" void kernel_launch(void* const* d_in, const int* in_sizes, int n_in,
                              void* d_out, int out_size) {
    // Identify inputs by element count (robust to metadata ordering).
    const float* x_freq  = nullptr;  int x_elems = 0;
    const float* weights = nullptr;  int w_elems = 0;
    for (int i = 0; i < n_in; i++) {
        if (in_sizes[i] >= NSTATES * NST && !x_freq) {
            x_freq = (const float*)d_in[i]; x_elems = in_sizes[i];
        } else if (in_sizes[i] == NLAYERS * NQ * 3 && !weights) {
            weights = (const float*)d_in[i]; w_elems = in_sizes[i];
        }
    }
    if (!x_freq || !weights) {
        int big = 0;
        for (int i = 1; i < n_in; i++) if (in_sizes[i] > in_sizes[big]) big = i;
        x_freq = (const float*)d_in[big]; x_elems = in_sizes[big];
        int sm = (big == 0 && n_in > 1) ? 1 : 0;
        weights = (const float*)d_in[sm]; w_elems = in_sizes[sm];
    }

    prep_gates_kernel<<<1, 64>>>(weights, w_elems);

    PParam pp;
    for (int i = 0; i < 32; i++) pp.lrow[i] = (unsigned short)PLAN.lrow[i];
    for (int i = 0; i < 32; i++) pp.jreg[i] = (unsigned short)PLAN.jreg[i];
    for (int b = 0; b < NQ; b++) pp.rlow[b] = (unsigned char)PLAN.rlow[b];

    // out_size == 2M -> real float32 output; >= 4M -> interleaved complex64.
    if (out_size <= NSTATES * NST)
        sim_kernel<0><<<NSTATES, BLOCK>>>(x_freq, x_elems, d_out, out_size, pp);
    else
        sim_kernel<1><<<NSTATES, BLOCK>>>(x_freq, x_elems, d_out, out_size, pp);
}